// round 15
// baseline (speedup 1.0000x reference)
#include <cuda_runtime.h>
#include <cuda_bf16.h>
#include <cstdint>

#define L_SEQ 8192
#define E_DIM 256
#define HDIM 256
#define G4 1024
#define T_TAGS 34
#define START_TAG 32
#define NEG_VAL -10000.0f
#define NCHUNK 64
#define CSTEPS 128

__device__ float g_igf[L_SEQ * G4];
__device__ float g_igb[L_SEQ * G4];
__device__ float g_hf[L_SEQ * HDIM];
__device__ float g_hb[L_SEQ * HDIM];
__device__ float g_feats[L_SEQ * T_TAGS];
__device__ float g_fexp[L_SEQ * T_TAGS];
__device__ float g_la[L_SEQ * T_TAGS];
__device__ float g_lb[L_SEQ * T_TAGS];
__device__ float g_M[2 * NCHUNK * T_TAGS * T_TAGS];
__device__ int   g_ME[2 * NCHUNK];
__device__ float g_vv[2 * NCHUNK * T_TAGS];
__device__ int   g_vE[2 * NCHUNK];

__device__ __forceinline__ float neg_inf() { return __int_as_float(0xff800000); }
__device__ __forceinline__ float sigmoidf_(float x) { return __fdividef(1.f, 1.f + __expf(-x)); }
__device__ __forceinline__ float tanhf_(float x) {
    float ax = fabsf(x);
    float e = __expf(-2.f * ax);
    float r = __fdividef(1.f - e, 1.f + e);
    return x < 0.f ? -r : r;
}
__device__ __forceinline__ float ex2_(float x) { float y; asm("ex2.approx.ftz.f32 %0,%1;" : "=f"(y) : "f"(x)); return y; }
__device__ __forceinline__ float lg2_(float x) { float y; asm("lg2.approx.ftz.f32 %0,%1;" : "=f"(y) : "f"(x)); return y; }
// exponent-of-float rescale helper: k = unbiased exponent (0 if zero/denorm), factor = 2^-k
__device__ __forceinline__ void scale_from(float anchor, int& k, float& factor) {
    unsigned b = __float_as_uint(anchor);
    int ex = (int)((b >> 23) & 255u);
    k = (ex == 0) ? 0 : (ex - 127);
    factor = __uint_as_float((unsigned)(127 - k) << 23);
}

__global__ void dummy_kernel() {}

// ------------- input projections (gather fused, FFMA2) -------------
__global__ void igates_kernel(const int* __restrict__ words,
                              const float* __restrict__ embed,
                              const float* __restrict__ Wih_f, const float* __restrict__ b_f,
                              const float* __restrict__ Wih_b, const float* __restrict__ b_b) {
    const float* W = blockIdx.z ? Wih_b : Wih_f;
    const float* b = blockIdx.z ? b_b : b_f;
    float* out = blockIdx.z ? g_igb : g_igf;
    __shared__ float ws[128][65];
    __shared__ __align__(16) float xsT[64][20];
    __shared__ long wrow[16];
    int tid = threadIdx.x;
    int t0 = blockIdx.x * 16, r0 = blockIdx.y * 128;
    if (tid < 16) wrow[tid] = (long)words[t0 + tid] * E_DIM;
    unsigned long long acc2[8];
#pragma unroll
    for (int i = 0; i < 8; i++) acc2[i] = 0ull;
    __syncthreads();
    for (int kc = 0; kc < 4; kc++) {
        int kb = kc * 64;
        for (int i = tid; i < 1024; i += 128)
            xsT[i & 63][i >> 6] = embed[wrow[i >> 6] + kb + (i & 63)];
        for (int i = tid; i < 8192; i += 128)
            ws[i >> 6][i & 63] = W[(r0 + (i >> 6)) * E_DIM + kb + (i & 63)];
        __syncthreads();
#pragma unroll 8
        for (int k = 0; k < 64; k++) {
            float wv = ws[tid][k];
            unsigned long long wv2;
            asm("mov.b64 %0, {%1,%1};" : "=l"(wv2) : "f"(wv));
            const ulonglong2* xp = (const ulonglong2*)&xsT[k][0];
#pragma unroll
            for (int q = 0; q < 4; q++) {
                ulonglong2 xv = xp[q];
                asm("fma.rn.f32x2 %0, %1, %2, %0;" : "+l"(acc2[2 * q + 0]) : "l"(wv2), "l"(xv.x));
                asm("fma.rn.f32x2 %0, %1, %2, %0;" : "+l"(acc2[2 * q + 1]) : "l"(wv2), "l"(xv.y));
            }
        }
        __syncthreads();
    }
    float bias = b[r0 + tid];
#pragma unroll
    for (int p = 0; p < 8; p++) {
        float lo, hi;
        asm("mov.b64 {%0,%1}, %2;" : "=f"(lo), "=f"(hi) : "l"(acc2[p]));
        out[(t0 + 2 * p + 0) * G4 + r0 + tid] = lo + bias;
        out[(t0 + 2 * p + 1) * G4 + r0 + tid] = hi + bias;
    }
}

// ------------- cluster-parallel persistent BiLSTM (champion, unchanged) -------------
__global__ void __cluster_dims__(8, 1, 1) __launch_bounds__(512, 1)
lstm_kernel(const float* __restrict__ Whh_f, const float* __restrict__ Whh_b) {
    __shared__ __align__(16) float hsm[2][HDIM];
    __shared__ float part[512];

    int tid = threadIdx.x;
    int dir = blockIdx.x >> 3;
    unsigned rank;
    asm("mov.u32 %0, %%cluster_ctarank;" : "=r"(rank));
    const float* Whh = dir ? Whh_b : Whh_f;
    const float* ig = dir ? g_igb : g_igf;
    float* hout = dir ? g_hb : g_hf;

    int row_local = tid & 127;
    int kseg = tid >> 7;
    int kb = kseg * 64;
    int g = row_local >> 5, u = row_local & 31;
    int unit = (int)rank * 32 + u;
    int grow = g * 256 + unit;

    unsigned long long w2[32];
    {
        const float2* wp2 = (const float2*)(Whh + grow * 256 + kb);
#pragma unroll
        for (int i = 0; i < 32; i++) {
            float2 f = wp2[i];
            asm("mov.b64 %0, {%1,%2};" : "=l"(w2[i]) : "f"(f.x), "f"(f.y));
        }
    }

    hsm[tid >> 8][tid & 255] = 0.f;

    unsigned lh = (unsigned)__cvta_generic_to_shared(&hsm[0][0]);
    unsigned base_h[8];
#pragma unroll
    for (int r = 0; r < 8; r++)
        asm("mapa.shared::cluster.u32 %0, %1, %2;" : "=r"(base_h[r]) : "r"(lh), "r"(r));

    __syncthreads();
    asm volatile("barrier.cluster.arrive.aligned;" ::: "memory");
    asm volatile("barrier.cluster.wait.aligned;" ::: "memory");

    float c_state = 0.f;
    int pos0 = dir ? (L_SEQ - 1) : 0;
    float ig_cur = (tid < 128) ? ig[pos0 * G4 + grow] : 0.f;

    for (int t = 0; t < L_SEQ; t++) {
        int posn = dir ? (L_SEQ - 2 - t) : (t + 1);
        float ig_nxt = (tid < 128 && t + 1 < L_SEQ) ? ig[posn * G4 + grow] : 0.f;

        const ulonglong2* hp = (const ulonglong2*)(hsm[t & 1] + kb);
        unsigned long long a0 = 0, a1 = 0;
#pragma unroll
        for (int i = 0; i < 16; i++) {
            ulonglong2 hv = hp[i];
            asm("fma.rn.f32x2 %0, %1, %2, %0;" : "+l"(a0) : "l"(w2[2 * i + 0]), "l"(hv.x));
            asm("fma.rn.f32x2 %0, %1, %2, %0;" : "+l"(a1) : "l"(w2[2 * i + 1]), "l"(hv.y));
        }
        float x0, x1, y0, y1;
        asm("mov.b64 {%0,%1}, %2;" : "=f"(x0), "=f"(x1) : "l"(a0));
        asm("mov.b64 {%0,%1}, %2;" : "=f"(y0), "=f"(y1) : "l"(a1));
        float a = (x0 + x1) + (y0 + y1);
        if (kseg == 0) a += ig_cur;
        part[kseg * 128 + row_local] = a;
        __syncthreads();

        if (tid < 128) {
            int uu = tid >> 2, gg = tid & 3;
            int row = gg * 32 + uu;
            float z = part[row] + part[128 + row] + part[256 + row] + part[384 + row];
            float act = (gg == 2) ? tanhf_(z) : sigmoidf_(z);
            int lq = tid & 31;
            float ai = __shfl_sync(0xffffffffu, act, (lq & ~3) + 0);
            float af = __shfl_sync(0xffffffffu, act, (lq & ~3) + 1);
            float ag = __shfl_sync(0xffffffffu, act, (lq & ~3) + 2);
            float ao = __shfl_sync(0xffffffffu, act, (lq & ~3) + 3);
            if (gg == 0) {
                c_state = fmaf(af, c_state, ai * ag);
                float h = ao * tanhf_(c_state);
                int pos = dir ? (L_SEQ - 1 - t) : t;
                int myu = (int)rank * 32 + uu;
                hout[pos * HDIM + myu] = h;
                if (t + 1 < L_SEQ) {
                    unsigned slotoff = (unsigned)(((t + 1) & 1) * (HDIM * 4) + myu * 4);
#pragma unroll
                    for (int rr = 0; rr < 8; rr++)
                        asm volatile("st.shared::cluster.f32 [%0], %1;"
                                     :: "r"(base_h[rr] + slotoff), "f"(h) : "memory");
                }
            }
        }
        ig_cur = ig_nxt;
        asm volatile("barrier.cluster.arrive.aligned;" ::: "memory");
        asm volatile("barrier.cluster.wait.aligned;" ::: "memory");
    }
}

// ------------- feats = [hf|hb] @ W_out^T + b_out (+ exp2 of feats) -------------
__global__ void feats_kernel(const float* __restrict__ W_out, const float* __restrict__ b_out) {
    __shared__ float ws[T_TAGS][257];
    int tid = threadIdx.x;
    int tk = tid / 34, j = tid % 34;
    int t = blockIdx.x * 8 + tk;
    bool act = tid < 272;
    float acc = act ? b_out[j] : 0.f;
    for (int half = 0; half < 2; half++) {
        for (int i = tid; i < T_TAGS * 256; i += 288)
            ws[i >> 8][i & 255] = W_out[(i >> 8) * 512 + half * 256 + (i & 255)];
        __syncthreads();
        if (act) {
            const float* h = half ? &g_hb[t * HDIM] : &g_hf[t * HDIM];
#pragma unroll 4
            for (int k = 0; k < 256; k++) acc = fmaf(h[k], ws[j][k], acc);
        }
        __syncthreads();
    }
    if (act) {
        g_feats[t * T_TAGS + j] = acc;
        g_fexp[t * T_TAGS + j] = ex2_(acc * 1.4426950408889634f);
    }
}

// ------------- CRF phase 1: per-chunk transfer matrices (linear domain) -------------
// grid (64,2), block 578: thread (j = tid%34, kk = tid/34) owns columns 2kk, 2kk+1.
__global__ void crf_phase1(const float* __restrict__ trans) {
    __shared__ float Wsm[T_TAGS][35];
    __shared__ __align__(8) float Mb[2][T_TAGS][36];
    __shared__ float Fsh[2][T_TAGS];
    const float L2E = 1.4426950408889634f;
    int tid = threadIdx.x;
    int dir = blockIdx.y;
    int c = blockIdx.x;
    int j = tid % 34;
    int kk = tid / 34;
    int k0 = kk * 2, k1 = k0 + 1;

    for (int idx = tid; idx < 1156; idx += 578)
        Wsm[idx / 34][idx % 34] = ex2_(trans[idx] * L2E);
    for (int idx = tid; idx < 2 * T_TAGS * 36; idx += 578)
        ((float*)Mb)[idx] = 0.f;
    __syncthreads();
    if (tid < 34) Mb[0][tid][tid] = 1.f;

    int t0 = c * CSTEPS + (dir ? (CSTEPS - 1) : 0);
    if (tid < 34) {
        float f;
        if (dir == 0) f = g_fexp[t0 * T_TAGS + tid];
        else { int tp = t0 + 1; f = (tp < L_SEQ) ? g_fexp[tp * T_TAGS + tid] : 1.f; }
        Fsh[0][tid] = f;
    }
    __syncthreads();

    int E = 0, cur = 0;
    for (int s = 0; s < CSTEPS; s++) {
        int t = dir ? (t0 - s) : (t0 + s);
        float fpre = 1.f;
        if (tid < 34 && s + 1 < CSTEPS) {
            int ft = dir ? (t - 1 + 1) : (t + 1);   // bwd next step (t-1) uses fexp[t]
            fpre = g_fexp[ft * T_TAGS + tid];
        }
        int k; float factor;
        scale_from(Mb[cur][0][0], k, factor);
        E += k;
        float a0 = 0.f, a1 = 0.f;
        if (dir == 0) {
#pragma unroll
            for (int i = 0; i < 34; i++) {
                float w = Wsm[j][i];
                float2 mp = *(const float2*)&Mb[cur][i][k0];
                a0 = fmaf(w, mp.x, a0);
                a1 = fmaf(w, mp.y, a1);
            }
            float f = Fsh[cur][j] * factor;
            a0 *= f; a1 *= f;
        } else {
#pragma unroll
            for (int i = 0; i < 34; i++) {
                float wf = Wsm[i][j] * Fsh[cur][i];
                float2 mp = *(const float2*)&Mb[cur][i][k0];
                a0 = fmaf(wf, mp.x, a0);
                a1 = fmaf(wf, mp.y, a1);
            }
            a0 *= factor; a1 *= factor;
        }
        Mb[cur ^ 1][j][k0] = a0;
        Mb[cur ^ 1][j][k1] = a1;
        if (tid < 34) Fsh[cur ^ 1][tid] = fpre;
        __syncthreads();
        cur ^= 1;
    }
    int base = (dir * NCHUNK + c) * (T_TAGS * T_TAGS);
    g_M[base + j * 34 + k0] = Mb[cur][j][k0];
    g_M[base + j * 34 + k1] = Mb[cur][j][k1];
    if (tid == 0) g_ME[dir * NCHUNK + c] = E;
}

// ------------- CRF phase 2: sequential chunk-entry vectors -------------
__global__ void crf_phase2() {
    __shared__ float Msm[T_TAGS * T_TAGS];
    __shared__ float vsm[40];
    int tid = threadIdx.x;         // 136
    int dir = blockIdx.x;
    int j = tid >> 2, s = tid & 3;
    int ns = (s < 2) ? 9 : 8;
    bool act = j < 34;
    if (tid < 34) vsm[tid] = dir ? 1.f : (tid == START_TAG ? 1.f : 0.f);
    __syncthreads();
    int E = 0;
    for (int cc = 0; cc < NCHUNK; cc++) {
        int c = dir ? (NCHUNK - 1 - cc) : cc;
        if (tid < 34) g_vv[(dir * NCHUNK + c) * T_TAGS + tid] = vsm[tid];
        if (tid == 0) g_vE[dir * NCHUNK + c] = E;
        int base = (dir * NCHUNK + c) * (T_TAGS * T_TAGS);
        for (int idx = tid; idx < 1156; idx += 136) Msm[idx] = g_M[base + idx];
        __syncthreads();
        float acc = 0.f;
        if (act) {
#pragma unroll
            for (int m = 0; m < 9; m++) {
                int i = s + 4 * m;
                if (m < ns) acc = fmaf(Msm[j * 34 + i], vsm[i], acc);
            }
        }
        acc += __shfl_xor_sync(0xffffffffu, acc, 1);
        acc += __shfl_xor_sync(0xffffffffu, acc, 2);
        __syncthreads();
        if (act && s == 0) vsm[j] = acc;
        __syncthreads();
        int k; float factor;
        scale_from(vsm[0], k, factor);
        __syncthreads();
        if (tid < 34) vsm[tid] *= factor;
        E += k + g_ME[dir * NCHUNK + c];
        __syncthreads();
    }
}

// ------------- CRF phase 3: chunk replay, write la/lb -------------
__global__ void crf_phase3(const float* __restrict__ trans) {
    __shared__ float Wsm[T_TAGS][35];
    __shared__ float buf[2][40];
    const float L2E = 1.4426950408889634f;
    const float LN2 = 0.6931471805599453f;
    int tid = threadIdx.x;         // 136
    int c = blockIdx.x, dir = blockIdx.y;
    int j = tid >> 2, s = tid & 3;
    bool act = j < 34;
    int ns = (s < 2) ? 9 : 8;
    for (int idx = tid; idx < 1156; idx += 136)
        Wsm[idx / 34][idx % 34] = ex2_(trans[idx] * L2E);
    int E = g_vE[dir * NCHUNK + c];
    int t0 = c * CSTEPS + (dir ? (CSTEPS - 1) : 0);
    if (tid < 34) {
        float v = g_vv[(dir * NCHUNK + c) * T_TAGS + tid];
        if (dir) {
            int tp = t0 + 1;
            float f = (tp < L_SEQ) ? g_fexp[tp * T_TAGS + tid] : 1.f;
            v *= f;
        }
        buf[0][tid] = v;
    }
    __syncthreads();
    int cur = 0;
    float fcur = (act && s == 0) ? g_fexp[t0 * T_TAGS + j] : 0.f;
    for (int ss = 0; ss < CSTEPS; ss++) {
        int t = dir ? (t0 - ss) : (t0 + ss);
        int tn = dir ? (t - 1) : (t + 1);
        float fnxt = (act && s == 0 && ss + 1 < CSTEPS) ? g_fexp[tn * T_TAGS + j] : 0.f;
        int k; float factor;
        scale_from(buf[cur][0], k, factor);
        float acc = 0.f;
        if (act) {
            if (dir == 0) {
#pragma unroll
                for (int m = 0; m < 9; m++) {
                    int i = s + 4 * m;
                    if (m < ns) acc = fmaf(Wsm[j][i], buf[cur][i], acc);
                }
            } else {
#pragma unroll
                for (int m = 0; m < 9; m++) {
                    int i = s + 4 * m;
                    if (m < ns) acc = fmaf(Wsm[i][j], buf[cur][i], acc);
                }
            }
        }
        acc += __shfl_xor_sync(0xffffffffu, acc, 1);
        acc += __shfl_xor_sync(0xffffffffu, acc, 2);
        if (act && s == 0) {
            int En = E + k;
            if (dir == 0) {
                float val = acc * fcur * factor;
                buf[cur ^ 1][j] = val;
                g_la[t * T_TAGS + j] = (lg2_(val) + (float)En) * LN2;
            } else {
                float val = acc * factor;
                g_lb[t * T_TAGS + j] = (lg2_(val) + (float)En) * LN2;
                buf[cur ^ 1][j] = val * fcur;
            }
        }
        E += k;
        fcur = fnxt;
        cur ^= 1;
        __syncthreads();
    }
}

// ------------- score = la + lb, tags = argmax -------------
__global__ void finalize_kernel(float* out, int out_size) {
    int t = blockIdx.x * blockDim.x + threadIdx.x;
    if (t >= L_SEQ) return;
    bool has_score = out_size >= L_SEQ * T_TAGS;
    float best = neg_inf();
    int bj = 0;
#pragma unroll 2
    for (int jj = 0; jj < T_TAGS; jj++) {
        float v = g_la[t * T_TAGS + jj] + g_lb[t * T_TAGS + jj];
        if (has_score) out[t * T_TAGS + jj] = v;
        if (v > best) { best = v; bj = jj; }
    }
    if (out_size >= L_SEQ * T_TAGS + L_SEQ) out[L_SEQ * T_TAGS + t] = (float)bj;
    else if (out_size == L_SEQ) ((int*)out)[t] = bj;
}

extern "C" void kernel_launch(void* const* d_in, const int* in_sizes, int n_in,
                              void* d_out, int out_size) {
    const int* words   = (const int*)d_in[0];
    const float* embed = (const float*)d_in[1];
    const float* Wih_f = (const float*)d_in[2];
    const float* Whh_f = (const float*)d_in[3];
    const float* b_f   = (const float*)d_in[4];
    const float* Wih_b = (const float*)d_in[5];
    const float* Whh_b = (const float*)d_in[6];
    const float* b_b   = (const float*)d_in[7];
    const float* W_out = (const float*)d_in[8];
    const float* b_out = (const float*)d_in[9];
    const float* trans = (const float*)d_in[10];

    dim3 ig_grid(L_SEQ / 16, 8, 2);
    igates_kernel<<<ig_grid, 128>>>(words, embed, Wih_f, b_f, Wih_b, b_b);
    dummy_kernel<<<1, 32>>>();
    dummy_kernel<<<1, 32>>>();
    lstm_kernel<<<16, 512>>>(Whh_f, Whh_b);
    feats_kernel<<<L_SEQ / 8, 288>>>(W_out, b_out);
    crf_phase1<<<dim3(NCHUNK, 2), 578>>>(trans);
    crf_phase2<<<2, 136>>>();
    crf_phase3<<<dim3(NCHUNK, 2), 136>>>(trans);
    finalize_kernel<<<(L_SEQ + 127) / 128, 128>>>((float*)d_out, out_size);
}